// round 2
// baseline (speedup 1.0000x reference)
#include <cuda_runtime.h>
#include <cuda_bf16.h>
#include <cstdint>
#include <cstddef>

#define BN 32
#define LN 2048
#define TN 2047          // number of key timesteps (L-1)
#define HN 512
#define CC 32            // chunk size
#define NCH 64           // TN chunks (last chunk has 1 padded row)
#define EPSV 1e-6f
#define GP 33            // padded Gram stride

// Static device scratch (allocation-free rule)
__device__ float g_Tinv[BN * NCH * CC * CC];   // 8 MB
__device__ float g_beta[BN * NCH * CC];
__device__ float g_ctx[BN * HN];

__device__ __forceinline__ float warp_sum(float v) {
    v += __shfl_xor_sync(0xffffffffu, v, 16);
    v += __shfl_xor_sync(0xffffffffu, v, 8);
    v += __shfl_xor_sync(0xffffffffu, v, 4);
    v += __shfl_xor_sync(0xffffffffu, v, 2);
    v += __shfl_xor_sync(0xffffffffu, v, 1);
    return v;
}

__device__ __forceinline__ void cp16(void* smem_dst, const void* gsrc) {
    unsigned sa = (unsigned)__cvta_generic_to_shared(smem_dst);
    asm volatile("cp.async.ca.shared.global [%0], [%1], 16;" :: "r"(sa), "l"(gsrc));
}
__device__ __forceinline__ void cp_commit() { asm volatile("cp.async.commit_group;"); }
__device__ __forceinline__ void cp_wait0()  { asm volatile("cp.async.wait_group 0;" ::: "memory"); }

// ---------------------------------------------------------------------------
// Phase A: per (chunk, batch): reversed-row Gram, betas, Tinv = (I+L)^-1.
// grid (NCH, BN), 256 threads.
// ---------------------------------------------------------------------------
__global__ void __launch_bounds__(256) gram_kernel(const float* __restrict__ hidden) {
    extern __shared__ float sm[];
    float* Ks    = sm;                 // [CC][HN]  reversed-time rows
    float* G     = sm + CC * HN;       // [CC][GP]  lower triangle
    float* betas = G + CC * GP;        // [CC]

    const int b = blockIdx.y, c = blockIdx.x;
    const int tid = threadIdx.x, wid = tid >> 5, lane = tid & 31;

    float4* Ks4 = reinterpret_cast<float4*>(Ks);
    for (int idx = tid; idx < CC * (HN / 4); idx += 256) {
        int row = idx >> 7;
        int col4 = idx & 127;
        int t = c * CC + (CC - 1) - row;
        float4 v = make_float4(0.f, 0.f, 0.f, 0.f);
        if (t < TN)
            v = *reinterpret_cast<const float4*>(hidden + (size_t)(b * LN + t) * HN + col4 * 4);
        Ks4[row * 128 + col4] = v;
    }
    __syncthreads();

    // Lower-triangular Gram: 36 4x4 blocks across 8 warps.
    for (int blk = wid; blk < 36; blk += 8) {
        int BI = 0, rem = blk;
        while (rem > BI) { BI++; rem -= BI; }
        int BJ = rem;

        float acc[4][4];
        #pragma unroll
        for (int i = 0; i < 4; i++)
            #pragma unroll
            for (int j = 0; j < 4; j++) acc[i][j] = 0.f;

        const float4* A4 = Ks4 + (4 * BI) * 128;
        const float4* B4 = Ks4 + (4 * BJ) * 128;
        #pragma unroll
        for (int stp = 0; stp < 4; stp++) {
            int hb = stp * 32 + lane;
            float4 av[4], bv[4];
            #pragma unroll
            for (int i = 0; i < 4; i++) av[i] = A4[i * 128 + hb];
            #pragma unroll
            for (int j = 0; j < 4; j++) bv[j] = B4[j * 128 + hb];
            #pragma unroll
            for (int i = 0; i < 4; i++)
                #pragma unroll
                for (int j = 0; j < 4; j++)
                    acc[i][j] += av[i].x * bv[j].x + av[i].y * bv[j].y +
                                 av[i].z * bv[j].z + av[i].w * bv[j].w;
        }
        #pragma unroll
        for (int i = 0; i < 4; i++)
            #pragma unroll
            for (int j = 0; j < 4; j++) {
                float v = warp_sum(acc[i][j]);
                if (lane == i * 4 + j) G[(4 * BI + i) * GP + (4 * BJ + j)] = v;
            }
    }
    __syncthreads();

    if (tid < CC) {
        float bt = 1.0f / (G[tid * GP + tid] + EPSV);
        betas[tid] = bt;
        g_beta[(b * NCH + c) * CC + tid] = bt;
    }
    __syncthreads();

    // Unit-lower-triangular inverse: column per lane (warp 0).
    if (wid == 0) {
        float* xs = Ks;  // reuse as [CC][GP]
        float* Tout = g_Tinv + (size_t)(b * NCH + c) * CC * CC;
        float x0 = (lane == 0) ? 1.f : 0.f;
        xs[lane] = x0;
        Tout[lane] = x0;
        for (int i = 1; i < CC; i++) {
            float acc = 0.f;
            for (int j = 0; j < i; j++)
                acc -= (G[i * GP + j] * betas[j]) * xs[j * GP + lane];
            float xi = (i > lane) ? acc : ((i == lane) ? 1.f : 0.f);
            xs[i * GP + lane] = xi;
            Tout[i * CC + lane] = xi;
        }
    }
}

// ---------------------------------------------------------------------------
// Phase B: backward chunked scan. grid BN, 512 threads, double-buffered.
//   m = K u ; s = Tinv m ; u -= K^T (beta .* s) ; ctx += K^T s
// ---------------------------------------------------------------------------
__global__ void __launch_bounds__(512) scan_kernel(const float* __restrict__ hidden) {
    extern __shared__ float sm[];
    float* Kb  = sm;                       // 2 * CC * HN
    float* Tb  = sm + 2 * CC * HN;         // 2 * CC * CC
    float* btb = Tb + 2 * CC * CC;         // 2 * CC
    float* us  = btb + 2 * CC;             // HN
    float* ms  = us + HN;                  // CC
    float* ss  = ms + CC;                  // CC
    float* sbs = ss + CC;                  // CC

    const int b = blockIdx.x;
    const int tid = threadIdx.x, wid = tid >> 5, lane = tid & 31;

    us[tid] = hidden[(size_t)(b * LN + (LN - 1)) * HN + tid];
    float racc = 0.f;

    const float* hb_base = hidden + (size_t)b * LN * HN;

    auto prefetch = [&](int c, int buf) {
        float* dstK = Kb + buf * (CC * HN);
        for (int idx = tid; idx < CC * (HN / 4); idx += 512) {
            int row = idx >> 7, col4 = idx & 127;
            int t = c * CC + (CC - 1) - row;
            float* dp = dstK + row * HN + col4 * 4;
            if (t < TN) cp16(dp, hb_base + (size_t)t * HN + col4 * 4);
            else *reinterpret_cast<float4*>(dp) = make_float4(0.f, 0.f, 0.f, 0.f);
        }
        const float* Tsrc = g_Tinv + (size_t)(b * NCH + c) * CC * CC;
        float* Tdst = Tb + buf * (CC * CC);
        for (int idx = tid; idx < CC * CC / 4; idx += 512)
            cp16(Tdst + idx * 4, Tsrc + idx * 4);
        if (tid < CC / 4)
            cp16(btb + buf * CC + tid * 4, g_beta + (size_t)(b * NCH + c) * CC + tid * 4);
        cp_commit();
    };

    prefetch(NCH - 1, (NCH - 1) & 1);

    for (int c = NCH - 1; c >= 0; c--) {
        const int buf = c & 1;
        cp_wait0();
        __syncthreads();
        if (c > 0) prefetch(c - 1, buf ^ 1);

        const float* K  = Kb + buf * (CC * HN);
        const float* Ti = Tb + buf * (CC * CC);
        const float* bt = btb + buf * CC;

        // m_j = K_j . u  (warp -> rows wid, wid+16)
        {
            const float4* K4 = reinterpret_cast<const float4*>(K);
            const float4* u4 = reinterpret_cast<const float4*>(us);
            int r0 = wid, r1 = wid + 16;
            float a0 = 0.f, a1 = 0.f;
            #pragma unroll
            for (int stp = 0; stp < 4; stp++) {
                int hb = stp * 32 + lane;
                float4 uv = u4[hb];
                float4 k0 = K4[r0 * 128 + hb];
                float4 k1 = K4[r1 * 128 + hb];
                a0 += k0.x * uv.x + k0.y * uv.y + k0.z * uv.z + k0.w * uv.w;
                a1 += k1.x * uv.x + k1.y * uv.y + k1.z * uv.z + k1.w * uv.w;
            }
            a0 = warp_sum(a0);
            a1 = warp_sum(a1);
            if (lane == 0) { ms[r0] = a0; ms[r1] = a1; }
        }
        __syncthreads();

        // s = Tinv * m ; sb = beta .* s
        {
            int r0 = wid, r1 = wid + 16;
            float mv = ms[lane];
            float a0 = Ti[r0 * CC + lane] * mv;
            float a1 = Ti[r1 * CC + lane] * mv;
            a0 = warp_sum(a0);
            a1 = warp_sum(a1);
            if (lane == 0) {
                ss[r0] = a0; sbs[r0] = a0 * bt[r0];
                ss[r1] = a1; sbs[r1] = a1 * bt[r1];
            }
        }
        __syncthreads();

        // u -= K^T sb ; ctx += K^T s   (thread owns H-column tid)
        {
            float ua = us[tid];
            #pragma unroll
            for (int j = 0; j < CC; j++) {
                float kv = K[j * HN + tid];
                ua   -= kv * sbs[j];
                racc += kv * ss[j];
            }
            us[tid] = ua;
        }
        __syncthreads();
    }
    g_ctx[b * HN + tid] = racc;
}

// ---------------------------------------------------------------------------
// Phase C: out[b,i] = ctx[b,:] . W[i,:] + bias[i]. grid BN, 256 threads.
// ---------------------------------------------------------------------------
__global__ void __launch_bounds__(256) out_kernel(const float* __restrict__ W,
                                                  const float* __restrict__ bias,
                                                  float* __restrict__ out) {
    __shared__ float cs[HN];
    const int b = blockIdx.x;
    for (int i = threadIdx.x; i < HN; i += 256) cs[i] = g_ctx[b * HN + i];
    __syncthreads();
    const int wid = threadIdx.x >> 5, lane = threadIdx.x & 31;
    const float4* c4 = reinterpret_cast<const float4*>(cs);
    for (int i = wid * 64; i < wid * 64 + 64; i++) {
        const float4* w4 = reinterpret_cast<const float4*>(W + (size_t)i * HN);
        float acc = 0.f;
        #pragma unroll
        for (int stp = 0; stp < 4; stp++) {
            float4 wv = w4[stp * 32 + lane];
            float4 cv = c4[stp * 32 + lane];
            acc += wv.x * cv.x + wv.y * cv.y + wv.z * cv.z + wv.w * cv.w;
        }
        acc = warp_sum(acc);
        if (lane == 0) out[b * HN + i] = acc + bias[i];
    }
}

extern "C" void kernel_launch(void* const* d_in, const int* in_sizes, int n_in,
                              void* d_out, int out_size) {
    const float* hidden = (const float*)d_in[0];
    const float* W      = (const float*)d_in[1];
    const float* bias   = (const float*)d_in[2];
    float* out          = (float*)d_out;

    const size_t smA = (size_t)(CC * HN + CC * GP + CC) * sizeof(float);            // ~68 KB
    const size_t smB = (size_t)(2 * CC * HN + 2 * CC * CC + 2 * CC + HN + 3 * CC)
                       * sizeof(float);                                             // ~139 KB

    cudaFuncSetAttribute(gram_kernel, cudaFuncAttributeMaxDynamicSharedMemorySize, (int)smA);
    cudaFuncSetAttribute(scan_kernel, cudaFuncAttributeMaxDynamicSharedMemorySize, (int)smB);

    gram_kernel<<<dim3(NCH, BN), 256, smA>>>(hidden);
    scan_kernel<<<BN, 512, smB>>>(hidden);
    out_kernel<<<BN, 256>>>(W, bias, out);
}